// round 1
// baseline (speedup 1.0000x reference)
#include <cuda_runtime.h>
#include <math.h>

#define D      512
#define LR     64
#define E      4
#define EL     256      // E * LR
#define CROSS  3
#define ROWS   64       // rows per CTA
#define THREADS 256
#define KB     8        // k-block per stage

// Scratch for transposed U weights: w2t[i][d][el] = Us[i][e][d][l], el = e*64+l
__device__ float g_w2t[CROSS * D * EL];
// Transposed gate: gwt[e][d] = gate_w[d][e]
__device__ float g_gwt[E * D];

__global__ void prep_kernel(const float* __restrict__ Us,
                            const float* __restrict__ gate_w) {
    int idx = blockIdx.x * blockDim.x + threadIdx.x;
    const int NW = CROSS * D * EL;
    if (idx < NW) {
        int i   = idx / (D * EL);
        int rem = idx % (D * EL);
        int d   = rem / EL;
        int el  = rem % EL;
        int e   = el / LR;
        int l   = el % LR;
        g_w2t[idx] = Us[((i * E + e) * D + d) * LR + l];
    } else if (idx < NW + E * D) {
        int j = idx - NW;
        int e = j / D, d = j % D;
        g_gwt[j] = gate_w[d * E + e];
    }
}

__device__ __forceinline__ float4 ld4(const float* p) {
    return *reinterpret_cast<const float4*>(p);
}

// Shared-memory GEMM: acc[8][8] += X[64 x KTOT] * W^T  (W is [256 cols][KTOT] K-major).
// Thread tile: 8 rows (warp picks row block) x 8 cols (lane*4..+3 and 128+lane*4..+3).
// BD = block-diagonal C-phase: X k-offset depends on the e-block of the column group.
template<int KTOT, int XS, bool BD>
__device__ __forceinline__ void gemm_acc(
    const float* __restrict__ Wg, int ws,
    const float* __restrict__ sX, float* __restrict__ sW,
    float acc[8][8], int tid)
{
    const int warp = tid >> 5, lane = tid & 31;
    const int r0 = warp * 8;
    const int cA = lane * 4, cB = 128 + cA;
    const int oA = BD ? ((cA >> 6) * LR) : 0;
    const int oB = BD ? ((cB >> 6) * LR) : 0;

    // prefetch first weight block
    float4 wa = ld4(Wg + tid * ws + 0);
    float4 wb = ld4(Wg + tid * ws + 4);

    #pragma unroll 1
    for (int kb = 0; kb < KTOT / KB; ++kb) {
        __syncthreads();                       // prior consumers of sW done
        sW[0*EL + tid] = wa.x; sW[1*EL + tid] = wa.y;
        sW[2*EL + tid] = wa.z; sW[3*EL + tid] = wa.w;
        sW[4*EL + tid] = wb.x; sW[5*EL + tid] = wb.y;
        sW[6*EL + tid] = wb.z; sW[7*EL + tid] = wb.w;
        if (kb + 1 < KTOT / KB) {              // overlap next global read w/ compute
            wa = ld4(Wg + tid * ws + (kb + 1) * KB);
            wb = ld4(Wg + tid * ws + (kb + 1) * KB + 4);
        }
        __syncthreads();

        #pragma unroll
        for (int h = 0; h < 2; ++h) {
            float4 xA[8], xB[8];
            #pragma unroll
            for (int i = 0; i < 8; ++i) {
                xA[i] = ld4(sX + (r0 + i) * XS + oA + kb * KB + h * 4);
                if (BD)
                    xB[i] = ld4(sX + (r0 + i) * XS + oB + kb * KB + h * 4);
            }
            #pragma unroll
            for (int kk = 0; kk < 4; ++kk) {
                float4 wA = ld4(sW + (h * 4 + kk) * EL + cA);
                float4 wB = ld4(sW + (h * 4 + kk) * EL + cB);
                #pragma unroll
                for (int i = 0; i < 8; ++i) {
                    float xa = (&xA[i].x)[kk];
                    float xb = BD ? (&xB[i].x)[kk] : xa;
                    acc[i][0] += xa * wA.x; acc[i][1] += xa * wA.y;
                    acc[i][2] += xa * wA.z; acc[i][3] += xa * wA.w;
                    acc[i][4] += xb * wB.x; acc[i][5] += xb * wB.y;
                    acc[i][6] += xb * wB.z; acc[i][7] += xb * wB.w;
                }
            }
        }
    }
}

#define ZERO_ACC(acc)                         \
    _Pragma("unroll")                         \
    for (int zi = 0; zi < 8; ++zi)            \
        _Pragma("unroll")                     \
        for (int zj = 0; zj < 8; ++zj)        \
            acc[zi][zj] = 0.f;

// smem floats: sXL 64*512, sACT 64*256, sW 8*256, sG 64*4, sGS 64
#define SMEM_FLOATS (ROWS * D + ROWS * EL + KB * EL + ROWS * E + ROWS)
#define SMEM_BYTES  (SMEM_FLOATS * 4)

__global__ void __launch_bounds__(THREADS, 1)
dcn_kernel(const float* __restrict__ x,
           const float* __restrict__ Vs,
           const float* __restrict__ Cs,
           const float* __restrict__ bias,
           float* __restrict__ out)
{
    extern __shared__ float smem[];
    float* sXL  = smem;                    // [ROWS][D]
    float* sACT = sXL  + ROWS * D;         // [ROWS][EL]
    float* sW   = sACT + ROWS * EL;        // [KB][EL]
    float* sG   = sW   + KB * EL;          // [ROWS][E]
    float* sGS  = sG   + ROWS * E;         // [ROWS]

    const int tid  = threadIdx.x;
    const int bid  = blockIdx.x;
    const int row0 = bid * ROWS;
    const int warp = tid >> 5, lane = tid & 31;
    const int r0 = warp * 8;
    const int cA = lane * 4, cB = 128 + cA;

    // Load x tile into sXL
    {
        const float4* src = reinterpret_cast<const float4*>(x + (size_t)row0 * D);
        float4* dst = reinterpret_cast<float4*>(sXL);
        for (int i = tid; i < ROWS * D / 4; i += THREADS) dst[i] = src[i];
    }

    float acc[8][8];

    for (int layer = 0; layer < CROSS; ++layer) {
        __syncthreads();   // sXL (prev layer epilogue / initial load) visible

        // ---- gate: g[r][e] = dot(x_l[r], gate_w[:,e]) ----
        {
            int r = tid >> 2, e = tid & 3;
            const float* xr = sXL + r * D;
            const float* gw = g_gwt + e * D;
            float g = 0.f;
            #pragma unroll 8
            for (int k = 0; k < D; k += 4) {
                float4 xv = ld4(xr + k);
                float4 wv = ld4(gw + k);
                g += xv.x * wv.x + xv.y * wv.y + xv.z * wv.z + xv.w * wv.w;
            }
            sG[tid] = g;
        }
        __syncthreads();
        if (tid < ROWS)
            sGS[tid] = sG[tid * 4] + sG[tid * 4 + 1] + sG[tid * 4 + 2] + sG[tid * 4 + 3];
        // (ordered by the sync inside the first gemm_acc iteration)

        // ---- V phase: v = tanh(Vs[i] @ x_l)  [64 x 256] ----
        ZERO_ACC(acc);
        gemm_acc<D, D, false>(Vs + (size_t)layer * EL * D, D, sXL, sW, acc, tid);
        #pragma unroll
        for (int i = 0; i < 8; ++i) {
            float4 va = make_float4(tanhf(acc[i][0]), tanhf(acc[i][1]),
                                    tanhf(acc[i][2]), tanhf(acc[i][3]));
            float4 vb = make_float4(tanhf(acc[i][4]), tanhf(acc[i][5]),
                                    tanhf(acc[i][6]), tanhf(acc[i][7]));
            *reinterpret_cast<float4*>(sACT + (r0 + i) * EL + cA) = va;
            *reinterpret_cast<float4*>(sACT + (r0 + i) * EL + cB) = vb;
        }

        // ---- C phase (block diagonal): c' = g_e * tanh(Cs[i,e] @ v_e) ----
        ZERO_ACC(acc);
        gemm_acc<LR, EL, true>(Cs + (size_t)layer * EL * LR, LR, sACT, sW, acc, tid);
        __syncthreads();   // all reads of v complete before overwrite
        {
            const int eA = cA >> 6, eB = cB >> 6;
            #pragma unroll
            for (int i = 0; i < 8; ++i) {
                float ga = sG[(r0 + i) * 4 + eA];
                float gb = sG[(r0 + i) * 4 + eB];
                float4 ca = make_float4(ga * tanhf(acc[i][0]), ga * tanhf(acc[i][1]),
                                        ga * tanhf(acc[i][2]), ga * tanhf(acc[i][3]));
                float4 cb = make_float4(gb * tanhf(acc[i][4]), gb * tanhf(acc[i][5]),
                                        gb * tanhf(acc[i][6]), gb * tanhf(acc[i][7]));
                *reinterpret_cast<float4*>(sACT + (r0 + i) * EL + cA) = ca;
                *reinterpret_cast<float4*>(sACT + (r0 + i) * EL + cB) = cb;
            }
        }

        // ---- U phase (two 256-col halves): x_l += x0*(U@c' + bias*sum_g) ----
        for (int half = 0; half < 2; ++half) {
            ZERO_ACC(acc);
            gemm_acc<EL, EL, false>(
                g_w2t + (size_t)layer * D * EL + (size_t)half * 256 * EL,
                EL, sACT, sW, acc, tid);
            #pragma unroll
            for (int i = 0; i < 8; ++i) {
                int r  = r0 + i;
                float gs = sGS[r];
                int dA = half * 256 + cA;
                int dB = half * 256 + cB;
                float4 bA  = ld4(bias + layer * D + dA);
                float4 bB  = ld4(bias + layer * D + dB);
                float4 x0A = ld4(x + (size_t)(row0 + r) * D + dA);
                float4 x0B = ld4(x + (size_t)(row0 + r) * D + dB);
                float4 xlA = ld4(sXL + r * D + dA);
                float4 xlB = ld4(sXL + r * D + dB);
                float4 oA, oB;
                oA.x = x0A.x * (acc[i][0] + bA.x * gs) + xlA.x;
                oA.y = x0A.y * (acc[i][1] + bA.y * gs) + xlA.y;
                oA.z = x0A.z * (acc[i][2] + bA.z * gs) + xlA.z;
                oA.w = x0A.w * (acc[i][3] + bA.w * gs) + xlA.w;
                oB.x = x0B.x * (acc[i][4] + bB.x * gs) + xlB.x;
                oB.y = x0B.y * (acc[i][5] + bB.y * gs) + xlB.y;
                oB.z = x0B.z * (acc[i][6] + bB.z * gs) + xlB.z;
                oB.w = x0B.w * (acc[i][7] + bB.w * gs) + xlB.w;
                *reinterpret_cast<float4*>(sXL + r * D + dA) = oA;
                *reinterpret_cast<float4*>(sXL + r * D + dB) = oB;
            }
        }
    }

    __syncthreads();
    {
        const float4* src = reinterpret_cast<const float4*>(sXL);
        float4* dst = reinterpret_cast<float4*>(out + (size_t)row0 * D);
        for (int i = tid; i < ROWS * D / 4; i += THREADS) dst[i] = src[i];
    }
}

extern "C" void kernel_launch(void* const* d_in, const int* in_sizes, int n_in,
                              void* d_out, int out_size) {
    const float* x    = (const float*)d_in[0];
    const float* Vs   = (const float*)d_in[1];
    const float* Cs   = (const float*)d_in[2];
    const float* Us   = (const float*)d_in[3];
    const float* bias = (const float*)d_in[4];
    const float* gate = (const float*)d_in[5];
    float* out = (float*)d_out;

    const int prep_total = CROSS * D * EL + E * D;
    prep_kernel<<<(prep_total + 255) / 256, 256>>>(Us, gate);

    int rows = in_sizes[0] / D;
    int grid = rows / ROWS;

    cudaFuncSetAttribute(dcn_kernel,
                         cudaFuncAttributeMaxDynamicSharedMemorySize, SMEM_BYTES);
    dcn_kernel<<<grid, THREADS, SMEM_BYTES>>>(x, Vs, Cs, bias, out);
}

// round 2
// speedup vs baseline: 1.0058x; 1.0058x over previous
#include <cuda_runtime.h>
#include <math.h>

#define D      512
#define LR     64
#define E      4
#define EL     256      // E * LR
#define CROSS  3
#define ROWS   64       // rows per CTA
#define THREADS 256
#define KB     8        // k-block per stage

typedef unsigned long long u64;

// Scratch for transposed U weights: w2t[i][d][el] = Us[i][e][d][l], el = e*64+l
__device__ float g_w2t[CROSS * D * EL];
// Transposed gate: gwt[e][d] = gate_w[d][e]
__device__ float g_gwt[E * D];

__global__ void prep_kernel(const float* __restrict__ Us,
                            const float* __restrict__ gate_w) {
    int idx = blockIdx.x * blockDim.x + threadIdx.x;
    const int NW = CROSS * D * EL;
    if (idx < NW) {
        int i   = idx / (D * EL);
        int rem = idx % (D * EL);
        int d   = rem / EL;
        int el  = rem % EL;
        int e   = el / LR;
        int l   = el % LR;
        g_w2t[idx] = Us[((i * E + e) * D + d) * LR + l];
    } else if (idx < NW + E * D) {
        int j = idx - NW;
        int e = j / D, d = j % D;
        g_gwt[j] = gate_w[d * E + e];
    }
}

__device__ __forceinline__ float4 ld4(const float* p) {
    return *reinterpret_cast<const float4*>(p);
}
__device__ __forceinline__ ulonglong2 ld2u64(const float* p) {
    return *reinterpret_cast<const ulonglong2*>(p);
}
__device__ __forceinline__ void ffma2(u64& acc, u64 a, u64 b) {
    asm("fma.rn.f32x2 %0, %1, %2, %0;" : "+l"(acc) : "l"(a), "l"(b));
}
__device__ __forceinline__ u64 pack2(float x) {
    u64 r;
    asm("mov.b64 %0, {%1, %1};" : "=l"(r) : "f"(x));
    return r;
}
__device__ __forceinline__ float2 unpack2(u64 v) {
    float2 r;
    asm("mov.b64 {%0, %1}, %2;" : "=f"(r.x), "=f"(r.y) : "l"(v));
    return r;
}
__device__ __forceinline__ float fast_tanh(float x) {
    asm("tanh.approx.f32 %0, %0;" : "+f"(x));
    return x;
}

// Shared-memory GEMM with packed f32x2 FMA:
// acc2[8 rows][4 col-pairs] += X[64 x KTOT] * W^T  (W is [256 cols][KTOT] K-major).
// Thread tile: 8 rows (warp picks row block) x 8 cols (lane*4..+3 and 128+lane*4..+3).
// BD = block-diagonal C-phase: X k-offset depends on the e-block of the column group.
template<int KTOT, int XS, bool BD>
__device__ __forceinline__ void gemm_acc(
    const float* __restrict__ Wg, int ws,
    const float* __restrict__ sX, float* __restrict__ sW,
    u64 acc2[8][4], int tid)
{
    const int warp = tid >> 5, lane = tid & 31;
    const int r0 = warp * 8;
    const int cA = lane * 4, cB = 128 + cA;
    const int oA = BD ? ((cA >> 6) * LR) : 0;
    const int oB = BD ? ((cB >> 6) * LR) : 0;

    // prefetch first weight block
    float4 wa = ld4(Wg + tid * ws + 0);
    float4 wb = ld4(Wg + tid * ws + 4);

    #pragma unroll 1
    for (int kb = 0; kb < KTOT / KB; ++kb) {
        __syncthreads();                       // prior consumers of sW done
        sW[0*EL + tid] = wa.x; sW[1*EL + tid] = wa.y;
        sW[2*EL + tid] = wa.z; sW[3*EL + tid] = wa.w;
        sW[4*EL + tid] = wb.x; sW[5*EL + tid] = wb.y;
        sW[6*EL + tid] = wb.z; sW[7*EL + tid] = wb.w;
        if (kb + 1 < KTOT / KB) {              // overlap next global read w/ compute
            wa = ld4(Wg + tid * ws + (kb + 1) * KB);
            wb = ld4(Wg + tid * ws + (kb + 1) * KB + 4);
        }
        __syncthreads();

        #pragma unroll
        for (int h = 0; h < 2; ++h) {
            float4 xA[8], xB[8];
            #pragma unroll
            for (int i = 0; i < 8; ++i) {
                xA[i] = ld4(sX + (r0 + i) * XS + oA + kb * KB + h * 4);
                if (BD)
                    xB[i] = ld4(sX + (r0 + i) * XS + oB + kb * KB + h * 4);
            }
            #pragma unroll
            for (int kk = 0; kk < 4; ++kk) {
                ulonglong2 wA = ld2u64(sW + (h * 4 + kk) * EL + cA);
                ulonglong2 wB = ld2u64(sW + (h * 4 + kk) * EL + cB);
                #pragma unroll
                for (int i = 0; i < 8; ++i) {
                    u64 xpa = pack2((&xA[i].x)[kk]);
                    u64 xpb = BD ? pack2((&xB[i].x)[kk]) : xpa;
                    ffma2(acc2[i][0], xpa, wA.x);
                    ffma2(acc2[i][1], xpa, wA.y);
                    ffma2(acc2[i][2], xpb, wB.x);
                    ffma2(acc2[i][3], xpb, wB.y);
                }
            }
        }
    }
}

#define ZERO_ACC(acc2)                        \
    _Pragma("unroll")                         \
    for (int zi = 0; zi < 8; ++zi)            \
        _Pragma("unroll")                     \
        for (int zj = 0; zj < 4; ++zj)        \
            acc2[zi][zj] = 0ull;

// smem floats: sXL 64*512, sACT 64*256, sW 8*256, sG 64*4, sGS 64
#define SMEM_FLOATS (ROWS * D + ROWS * EL + KB * EL + ROWS * E + ROWS)
#define SMEM_BYTES  (SMEM_FLOATS * 4)

__global__ void __launch_bounds__(THREADS, 1)
dcn_kernel(const float* __restrict__ x,
           const float* __restrict__ Vs,
           const float* __restrict__ Cs,
           const float* __restrict__ bias,
           float* __restrict__ out)
{
    extern __shared__ float smem[];
    float* sXL  = smem;                    // [ROWS][D]
    float* sACT = sXL  + ROWS * D;         // [ROWS][EL]
    float* sW   = sACT + ROWS * EL;        // [KB][EL]
    float* sG   = sW   + KB * EL;          // [ROWS][E]
    float* sGS  = sG   + ROWS * E;         // [ROWS]

    const int tid  = threadIdx.x;
    const int bid  = blockIdx.x;
    const int row0 = bid * ROWS;
    const int warp = tid >> 5, lane = tid & 31;
    const int r0 = warp * 8;
    const int cA = lane * 4, cB = 128 + cA;

    // Load x tile into sXL
    {
        const float4* src = reinterpret_cast<const float4*>(x + (size_t)row0 * D);
        float4* dst = reinterpret_cast<float4*>(sXL);
        for (int i = tid; i < ROWS * D / 4; i += THREADS) dst[i] = src[i];
    }

    u64 acc2[8][4];

    for (int layer = 0; layer < CROSS; ++layer) {
        __syncthreads();   // sXL (prev layer epilogue / initial load) visible

        // ---- gate: g[r][e] = dot(x_l[r], gate_w[:,e]) ----
        {
            int r = tid >> 2, e = tid & 3;
            const float* xr = sXL + r * D;
            const float* gw = g_gwt + e * D;
            float g = 0.f;
            #pragma unroll 8
            for (int k = 0; k < D; k += 4) {
                float4 xv = ld4(xr + k);
                float4 wv = ld4(gw + k);
                g += xv.x * wv.x + xv.y * wv.y + xv.z * wv.z + xv.w * wv.w;
            }
            sG[tid] = g;
        }
        __syncthreads();
        if (tid < ROWS)
            sGS[tid] = sG[tid * 4] + sG[tid * 4 + 1] + sG[tid * 4 + 2] + sG[tid * 4 + 3];
        // (ordered by the sync inside the first gemm_acc iteration)

        // ---- V phase: v = tanh(Vs[i] @ x_l)  [64 x 256] ----
        ZERO_ACC(acc2);
        gemm_acc<D, D, false>(Vs + (size_t)layer * EL * D, D, sXL, sW, acc2, tid);
        #pragma unroll
        for (int i = 0; i < 8; ++i) {
            float2 p0 = unpack2(acc2[i][0]), p1 = unpack2(acc2[i][1]);
            float2 p2 = unpack2(acc2[i][2]), p3 = unpack2(acc2[i][3]);
            float4 va = make_float4(fast_tanh(p0.x), fast_tanh(p0.y),
                                    fast_tanh(p1.x), fast_tanh(p1.y));
            float4 vb = make_float4(fast_tanh(p2.x), fast_tanh(p2.y),
                                    fast_tanh(p3.x), fast_tanh(p3.y));
            *reinterpret_cast<float4*>(sACT + (r0 + i) * EL + cA) = va;
            *reinterpret_cast<float4*>(sACT + (r0 + i) * EL + cB) = vb;
        }

        // ---- C phase (block diagonal): c' = g_e * tanh(Cs[i,e] @ v_e) ----
        ZERO_ACC(acc2);
        gemm_acc<LR, EL, true>(Cs + (size_t)layer * EL * LR, LR, sACT, sW, acc2, tid);
        __syncthreads();   // all reads of v complete before overwrite
        {
            const int eA = cA >> 6, eB = cB >> 6;
            #pragma unroll
            for (int i = 0; i < 8; ++i) {
                float ga = sG[(r0 + i) * 4 + eA];
                float gb = sG[(r0 + i) * 4 + eB];
                float2 p0 = unpack2(acc2[i][0]), p1 = unpack2(acc2[i][1]);
                float2 p2 = unpack2(acc2[i][2]), p3 = unpack2(acc2[i][3]);
                float4 ca = make_float4(ga * fast_tanh(p0.x), ga * fast_tanh(p0.y),
                                        ga * fast_tanh(p1.x), ga * fast_tanh(p1.y));
                float4 cb = make_float4(gb * fast_tanh(p2.x), gb * fast_tanh(p2.y),
                                        gb * fast_tanh(p3.x), gb * fast_tanh(p3.y));
                *reinterpret_cast<float4*>(sACT + (r0 + i) * EL + cA) = ca;
                *reinterpret_cast<float4*>(sACT + (r0 + i) * EL + cB) = cb;
            }
        }

        // ---- U phase (two 256-col halves): x_l += x0*(U@c' + bias*sum_g) ----
        for (int half = 0; half < 2; ++half) {
            ZERO_ACC(acc2);
            gemm_acc<EL, EL, false>(
                g_w2t + (size_t)layer * D * EL + (size_t)half * 256 * EL,
                EL, sACT, sW, acc2, tid);
            #pragma unroll
            for (int i = 0; i < 8; ++i) {
                int r  = r0 + i;
                float gs = sGS[r];
                int dA = half * 256 + cA;
                int dB = half * 256 + cB;
                float2 p0 = unpack2(acc2[i][0]), p1 = unpack2(acc2[i][1]);
                float2 p2 = unpack2(acc2[i][2]), p3 = unpack2(acc2[i][3]);
                float4 bA  = ld4(bias + layer * D + dA);
                float4 bB  = ld4(bias + layer * D + dB);
                float4 x0A = ld4(x + (size_t)(row0 + r) * D + dA);
                float4 x0B = ld4(x + (size_t)(row0 + r) * D + dB);
                float4 xlA = ld4(sXL + r * D + dA);
                float4 xlB = ld4(sXL + r * D + dB);
                float4 oA, oB;
                oA.x = x0A.x * (p0.x + bA.x * gs) + xlA.x;
                oA.y = x0A.y * (p0.y + bA.y * gs) + xlA.y;
                oA.z = x0A.z * (p1.x + bA.z * gs) + xlA.z;
                oA.w = x0A.w * (p1.y + bA.w * gs) + xlA.w;
                oB.x = x0B.x * (p2.x + bB.x * gs) + xlB.x;
                oB.y = x0B.y * (p2.y + bB.y * gs) + xlB.y;
                oB.z = x0B.z * (p3.x + bB.z * gs) + xlB.z;
                oB.w = x0B.w * (p3.y + bB.w * gs) + xlB.w;
                *reinterpret_cast<float4*>(sXL + r * D + dA) = oA;
                *reinterpret_cast<float4*>(sXL + r * D + dB) = oB;
            }
        }
    }

    __syncthreads();
    {
        const float4* src = reinterpret_cast<const float4*>(sXL);
        float4* dst = reinterpret_cast<float4*>(out + (size_t)row0 * D);
        for (int i = tid; i < ROWS * D / 4; i += THREADS) dst[i] = src[i];
    }
}

extern "C" void kernel_launch(void* const* d_in, const int* in_sizes, int n_in,
                              void* d_out, int out_size) {
    const float* x    = (const float*)d_in[0];
    const float* Vs   = (const float*)d_in[1];
    const float* Cs   = (const float*)d_in[2];
    const float* Us   = (const float*)d_in[3];
    const float* bias = (const float*)d_in[4];
    const float* gate = (const float*)d_in[5];
    float* out = (float*)d_out;

    const int prep_total = CROSS * D * EL + E * D;
    prep_kernel<<<(prep_total + 255) / 256, 256>>>(Us, gate);

    int rows = in_sizes[0] / D;
    int grid = rows / ROWS;

    cudaFuncSetAttribute(dcn_kernel,
                         cudaFuncAttributeMaxDynamicSharedMemorySize, SMEM_BYTES);
    dcn_kernel<<<grid, THREADS, SMEM_BYTES>>>(x, Vs, Cs, bias, out);
}